// round 16
// baseline (speedup 1.0000x reference)
#include <cuda_runtime.h>
#include <cuda_bf16.h>
#include <cuda_fp16.h>
#include <cstdint>

// ---------------- fixed problem shapes ----------------
#define N_NODES 100000
#define D 64
#define E_EDGES 1600000
#define MSG_H 128
#define MSG_OUT 64
#define NODE_H 128
#define LN_EPS 1e-5f

// ---------------- device scratch ----------------
__device__ __align__(16) float g_Ps[(size_t)N_NODES * 128];  // nodes @ W1[0:64,:]
__device__ __align__(16) float g_Pr[(size_t)N_NODES * 128];  // nodes @ W1[64:128,:] + b1
__device__ __align__(16) float g_agg[(size_t)N_NODES * 64];  // segment-sum of messages

// =====================================================================
// helpers (sm_80/sm_90 baseline features -> compile for compute_103)
// =====================================================================
__device__ __forceinline__ uint32_t smem_u32(const void* p) {
    uint32_t a;
    asm("{ .reg .u64 t; cvta.to.shared.u64 t, %1; cvt.u32.u64 %0, t; }" : "=r"(a) : "l"(p));
    return a;
}

__device__ __forceinline__ void ldmx4(uint32_t* r, uint32_t addr) {
    asm volatile("ldmatrix.sync.aligned.m8n8.x4.shared.b16 {%0,%1,%2,%3}, [%4];"
                 : "=r"(r[0]), "=r"(r[1]), "=r"(r[2]), "=r"(r[3]) : "r"(addr));
}

// bf16 mma (node kernel)
__device__ __forceinline__ void mma16816(float* d, const uint32_t* a, uint32_t b0, uint32_t b1) {
    asm volatile(
        "mma.sync.aligned.m16n8k16.row.col.f32.bf16.bf16.f32 "
        "{%0,%1,%2,%3}, {%4,%5,%6,%7}, {%8,%9}, {%0,%1,%2,%3};"
        : "+f"(d[0]), "+f"(d[1]), "+f"(d[2]), "+f"(d[3])
        : "r"(a[0]), "r"(a[1]), "r"(a[2]), "r"(a[3]), "r"(b0), "r"(b1));
}

// fp16 mma (edge kernel)
__device__ __forceinline__ void mma16816h(float* d, const uint32_t* a, uint32_t b0, uint32_t b1) {
    asm volatile(
        "mma.sync.aligned.m16n8k16.row.col.f32.f16.f16.f32 "
        "{%0,%1,%2,%3}, {%4,%5,%6,%7}, {%8,%9}, {%0,%1,%2,%3};"
        : "+f"(d[0]), "+f"(d[1]), "+f"(d[2]), "+f"(d[3])
        : "r"(a[0]), "r"(a[1]), "r"(a[2]), "r"(a[3]), "r"(b0), "r"(b1));
}

__device__ __forceinline__ void bfsplit2(float x0, float x1, uint32_t& hi, uint32_t& lo) {
    __nv_bfloat162 h = __floats2bfloat162_rn(x0, x1);
    float r0 = x0 - __low2float(h);
    float r1 = x1 - __high2float(h);
    __nv_bfloat162 l = __floats2bfloat162_rn(r0, r1);
    hi = reinterpret_cast<uint32_t&>(h);
    lo = reinterpret_cast<uint32_t&>(l);
}

__device__ __forceinline__ void f16split2(float x0, float x1, uint32_t& hi, uint32_t& lo) {
    __half2 h = __floats2half2_rn(x0, x1);
    float r0 = x0 - __low2float(h);
    float r1 = x1 - __high2float(h);
    __half2 l = __floats2half2_rn(r0, r1);
    hi = reinterpret_cast<uint32_t&>(h);
    lo = reinterpret_cast<uint32_t&>(l);
}

__device__ __forceinline__ uint32_t f16pack2(float x0, float x1) {
    __half2 h = __floats2half2_rn(x0, x1);
    return reinterpret_cast<uint32_t&>(h);
}

__device__ __forceinline__ void red_add_v2(float* gptr, float a, float b) {
    asm volatile("red.global.add.v2.f32 [%0], {%1, %2};"
                 :: "l"(gptr), "f"(a), "f"(b) : "memory");
}

// =====================================================================
// Kernel 0: zero aggregation buffer
// =====================================================================
__global__ void zero_agg_kernel() {
    float4* p = reinterpret_cast<float4*>(g_agg);
    const int n4 = N_NODES * 64 / 4;
    for (int i = blockIdx.x * blockDim.x + threadIdx.x; i < n4; i += gridDim.x * blockDim.x)
        p[i] = make_float4(0.f, 0.f, 0.f, 0.f);
}

// =====================================================================
// Kernel 1: node projections (fp32 FFMA; 3.3 GFLOP total)
// =====================================================================
__global__ __launch_bounds__(256, 3)
void proj_kernel(const float* __restrict__ nodes,
                 const float* __restrict__ msg_W1,
                 const float* __restrict__ msg_b1)
{
    extern __shared__ float sm[];
    float* sW = sm;
    float* sN = sm + 128 * 128;

    const int tid = threadIdx.x;
    for (int i = tid; i < 128 * 128; i += 256) sW[i] = msg_W1[i];
    __syncthreads();

    const int sub = tid >> 7;
    const int c   = tid & 127;
    const float bias = msg_b1[c];

    const int numPairs = N_NODES / 2;
    for (int p = blockIdx.x; p < numPairs; p += gridDim.x) {
        const int n0 = p * 2;
        if (tid < 128) sN[tid] = nodes[(size_t)n0 * 64 + tid];
        __syncthreads();
        float as = 0.f, ar = 0.f;
        const float* nr = &sN[sub * 64];
        #pragma unroll 8
        for (int k = 0; k < 64; ++k) {
            const float a = nr[k];
            as = fmaf(a, sW[k * 128 + c], as);
            ar = fmaf(a, sW[(64 + k) * 128 + c], ar);
        }
        const int n = n0 + sub;
        g_Ps[(size_t)n * 128 + c] = as;
        g_Pr[(size_t)n * 128 + c] = ar + bias;
        __syncthreads();
    }
}

// =====================================================================
// Kernel 2: edge message MLP. R16: fp16 arithmetic + 64-edge tiles ->
// smem 105 KB -> 2 CTAs/SM (barrier phases of one CTA overlap the
// other's MMA). GEMM1: 3-term fp16 (A hi/lo, W1 hi/lo). GEMM2: 2-term
// (h single fp16, W2 hi/lo). Gather-hiding + reg scatter from R14/R15.
// =====================================================================
#define OFF_B2   0
#define OFF_AH   256
#define OFF_AL   (OFF_AH  + 9216)
#define OFF_W1H  (OFF_AL  + 9216)
#define OFF_W1L  (OFF_W1H + 18432)
#define OFF_W2H  (OFF_W1L + 18432)
#define OFF_W2L  (OFF_W2H + 17408)
#define OFF_H    (OFF_W2L + 17408)
#define EDGE_SMEM_BYTES (OFF_H + 17408)   // 107776 bytes -> 2 CTAs/SM

__global__ __launch_bounds__(256, 2)
void edge_kernel(const float* __restrict__ edges,
                 const int* __restrict__ senders,
                 const int* __restrict__ receivers,
                 const float* __restrict__ msg_W1,
                 const float* __restrict__ msg_W2,
                 const float* __restrict__ msg_b2)
{
    extern __shared__ char smc[];
    const uint32_t sb = smem_u32(smc);
    const int tid  = threadIdx.x;
    const int warp = tid >> 5;        // 0..7
    const int lane = tid & 31;
    const int mw   = warp >> 1;       // 0..3 : 16-edge m-tile (64-edge tile)
    const int nw   = warp & 1;        // 0..1 : N-half
    const int g    = lane >> 2;       // groupID
    const int tg   = lane & 3;        // threadID-in-group
    const int qq   = lane >> 3;       // ldmatrix quadrant
    const int lr   = lane & 7;        // row within quadrant

    float* sB2 = reinterpret_cast<float*>(smc + OFF_B2);
    if (tid < 64) sB2[tid] = msg_b2[tid];

    // ---- stage W1e^T as [n=128][k=64] fp16 hi/lo, stride 72 ----
    for (int i = tid; i < 128 * 64; i += 256) {
        const int n = i >> 6, k = i & 63;
        const float w = msg_W1[(128 + k) * 128 + n];
        const __half h = __float2half_rn(w);
        const __half l = __float2half_rn(w - __half2float(h));
        *reinterpret_cast<__half*>(smc + OFF_W1H + (n * 72 + k) * 2) = h;
        *reinterpret_cast<__half*>(smc + OFF_W1L + (n * 72 + k) * 2) = l;
    }
    // ---- stage W2^T as [n=64][k=128] fp16 hi/lo, stride 136 ----
    for (int i = tid; i < 64 * 128; i += 256) {
        const int n = i >> 7, k = i & 127;
        const float w = msg_W2[k * 64 + n];
        const __half h = __float2half_rn(w);
        const __half l = __float2half_rn(w - __half2float(h));
        *reinterpret_cast<__half*>(smc + OFF_W2H + (n * 136 + k) * 2) = h;
        *reinterpret_cast<__half*>(smc + OFF_W2L + (n * 136 + k) * 2) = l;
    }

    const int er0 = mw * 16 + g;   // this lane's two edge rows (0..63)
    const int er1 = er0 + 8;
    const int nb1 = nw * 64;       // GEMM1 col base (8 nf of 8)
    const int nb2 = nw * 32;       // GEMM2 col base (4 nf of 8)

    const int numTiles = E_EDGES / 64;  // 25000
    for (int tile = blockIdx.x; tile < numTiles; tile += gridDim.x) {
        const int e0 = tile * 64;

        // ---- ids via direct LDG ----
        const int s0 = __ldg(&senders[e0 + er0]);
        const int r0 = __ldg(&receivers[e0 + er0]);
        const int s1 = __ldg(&senders[e0 + er1]);
        const int r1 = __ldg(&receivers[e0 + er1]);

        // ---- issue Ps/Pr gathers NOW; land during staging + GEMM1 ----
        float pg[8][4];
        {
            const float* ps0 = &g_Ps[(size_t)s0 * 128];
            const float* pr0 = &g_Pr[(size_t)r0 * 128];
            const float* ps1 = &g_Ps[(size_t)s1 * 128];
            const float* pr1 = &g_Pr[(size_t)r1 * 128];
            #pragma unroll
            for (int nf = 0; nf < 8; ++nf) {
                const int n = nb1 + nf * 8 + tg * 2;
                const float2 a0 = *reinterpret_cast<const float2*>(ps0 + n);
                const float2 b0 = *reinterpret_cast<const float2*>(pr0 + n);
                const float2 a1 = *reinterpret_cast<const float2*>(ps1 + n);
                const float2 b1 = *reinterpret_cast<const float2*>(pr1 + n);
                pg[nf][0] = a0.x + b0.x;
                pg[nf][1] = a0.y + b0.y;
                pg[nf][2] = a1.x + b1.x;
                pg[nf][3] = a1.y + b1.y;
            }
        }

        __syncthreads();  // prior tile's smem reads complete

        // ---- stage edge tile [64][64] -> fp16 hi/lo (stride 72) ----
        {
            const int row = tid >> 2, q = tid & 3;    // 64 rows x 4 chunks
            const float4* src = reinterpret_cast<const float4*>(
                &edges[(size_t)(e0 + row) * 64 + q * 16]);
            uint32_t hi[8], lo[8];
            #pragma unroll
            for (int j = 0; j < 4; ++j) {
                const float4 f = src[j];
                f16split2(f.x, f.y, hi[2 * j],     lo[2 * j]);
                f16split2(f.z, f.w, hi[2 * j + 1], lo[2 * j + 1]);
            }
            char* dh = smc + OFF_AH + row * 144 + q * 32;
            char* dl = smc + OFF_AL + row * 144 + q * 32;
            *reinterpret_cast<uint4*>(dh)      = make_uint4(hi[0], hi[1], hi[2], hi[3]);
            *reinterpret_cast<uint4*>(dh + 16) = make_uint4(hi[4], hi[5], hi[6], hi[7]);
            *reinterpret_cast<uint4*>(dl)      = make_uint4(lo[0], lo[1], lo[2], lo[3]);
            *reinterpret_cast<uint4*>(dl + 16) = make_uint4(lo[4], lo[5], lo[6], lo[7]);
        }
        __syncthreads();

        // ============ GEMM1 (3-term fp16): 16 edges x 64 cols ============
        float acc[8][4];
        #pragma unroll
        for (int nf = 0; nf < 8; ++nf)
            #pragma unroll
            for (int j = 0; j < 4; ++j) acc[nf][j] = 0.f;

        #pragma unroll
        for (int kt = 0; kt < 4; ++kt) {
            const int k0 = kt * 16;
            const uint32_t ao = (uint32_t)(((mw * 16 + (qq & 1) * 8 + lr) * 72
                                            + k0 + (qq >> 1) * 8) * 2);
            uint32_t Ah[4], Al[4];
            ldmx4(Ah, sb + OFF_AH + ao);
            ldmx4(Al, sb + OFF_AL + ao);
            #pragma unroll
            for (int nf = 0; nf < 8; ++nf) {
                const uint32_t bo = (uint32_t)(((nb1 + nf * 8 + g) * 72 + k0 + tg * 2) * 2);
                const uint32_t bh0 = *reinterpret_cast<const uint32_t*>(smc + OFF_W1H + bo);
                const uint32_t bh1 = *reinterpret_cast<const uint32_t*>(smc + OFF_W1H + bo + 16);
                const uint32_t bl0 = *reinterpret_cast<const uint32_t*>(smc + OFF_W1L + bo);
                const uint32_t bl1 = *reinterpret_cast<const uint32_t*>(smc + OFF_W1L + bo + 16);
                mma16816h(acc[nf], Ah, bh0, bh1);
                mma16816h(acc[nf], Ah, bl0, bl1);
                mma16816h(acc[nf], Al, bh0, bh1);
            }
        }
        // epilogue1: += gathered Ps+Pr, relu -> SINGLE fp16 h (272 B rows)
        #pragma unroll
        for (int nf = 0; nf < 8; ++nf) {
            const int n = nb1 + nf * 8 + tg * 2;
            *reinterpret_cast<uint32_t*>(smc + OFF_H + er0 * 272 + n * 2) =
                f16pack2(fmaxf(acc[nf][0] + pg[nf][0], 0.f),
                         fmaxf(acc[nf][1] + pg[nf][1], 0.f));
            *reinterpret_cast<uint32_t*>(smc + OFF_H + er1 * 272 + n * 2) =
                f16pack2(fmaxf(acc[nf][2] + pg[nf][2], 0.f),
                         fmaxf(acc[nf][3] + pg[nf][3], 0.f));
        }
        __syncthreads();

        // ============ GEMM2 (2-term fp16): 16 edges x 32 cols ============
        float acc2[4][4];
        #pragma unroll
        for (int nf = 0; nf < 4; ++nf) {
            const int n = nb2 + nf * 8 + tg * 2;
            const float b0 = sB2[n], b1 = sB2[n + 1];
            acc2[nf][0] = b0; acc2[nf][1] = b1;
            acc2[nf][2] = b0; acc2[nf][3] = b1;
        }
        #pragma unroll
        for (int kt = 0; kt < 8; ++kt) {
            const int k0 = kt * 16;
            const uint32_t ao = (uint32_t)(((mw * 16 + (qq & 1) * 8 + lr) * 136
                                            + k0 + (qq >> 1) * 8) * 2);
            uint32_t Ah[4];
            ldmx4(Ah, sb + OFF_H + ao);
            #pragma unroll
            for (int nf = 0; nf < 4; ++nf) {
                const uint32_t bo = (uint32_t)(((nb2 + nf * 8 + g) * 136 + k0 + tg * 2) * 2);
                const uint32_t bh0 = *reinterpret_cast<const uint32_t*>(smc + OFF_W2H + bo);
                const uint32_t bh1 = *reinterpret_cast<const uint32_t*>(smc + OFF_W2H + bo + 16);
                const uint32_t bl0 = *reinterpret_cast<const uint32_t*>(smc + OFF_W2L + bo);
                const uint32_t bl1 = *reinterpret_cast<const uint32_t*>(smc + OFF_W2L + bo + 16);
                mma16816h(acc2[nf], Ah, bh0, bh1);
                mma16816h(acc2[nf], Ah, bl0, bl1);
            }
        }
        // epilogue2: relu, vectorized scatter straight from registers
        #pragma unroll
        for (int nf = 0; nf < 4; ++nf) {
            const int n = nb2 + nf * 8 + tg * 2;
            red_add_v2(&g_agg[(size_t)r0 * 64 + n],
                       fmaxf(acc2[nf][0], 0.f), fmaxf(acc2[nf][1], 0.f));
            red_add_v2(&g_agg[(size_t)r1 * 64 + n],
                       fmaxf(acc2[nf][2], 0.f), fmaxf(acc2[nf][3], 0.f));
        }
    }
}

// =====================================================================
// Kernel 3: node update MLP via warp-MMA (unchanged, ~94us)
// =====================================================================
#define NOFF_B1   0
#define NOFF_B2   512
#define NOFF_LNS  768
#define NOFF_LNO  1024
#define NOFF_W1H  1280
#define NOFF_W1L  (NOFF_W1H + 34816)
#define NOFF_W2H  (NOFF_W1L + 34816)
#define NOFF_W2L  (NOFF_W2H + 17408)
#define NOFF_XH   (NOFF_W2L + 17408)
#define NOFF_XL   (NOFF_XH  + 34816)
#define NOFF_Y    (NOFF_XL  + 34816)
#define NODE_SMEM_BYTES (NOFF_Y + 34816)   // 210176

__global__ __launch_bounds__(256, 1)
void node_mma_kernel(const float* __restrict__ nodes,
                     const float* __restrict__ node_W1,
                     const float* __restrict__ node_b1,
                     const float* __restrict__ node_W2,
                     const float* __restrict__ node_b2,
                     const float* __restrict__ ln_scale,
                     const float* __restrict__ ln_offset,
                     float* __restrict__ out)
{
    extern __shared__ char smc[];
    const uint32_t sb = smem_u32(smc);
    const int tid  = threadIdx.x;
    const int warp = tid >> 5;
    const int lane = tid & 31;
    const int g    = lane >> 2;
    const int tg   = lane & 3;
    const int qq   = lane >> 3;
    const int lr   = lane & 7;

    float* sB1  = reinterpret_cast<float*>(smc + NOFF_B1);
    float* sB2  = reinterpret_cast<float*>(smc + NOFF_B2);
    float* sLNs = reinterpret_cast<float*>(smc + NOFF_LNS);
    float* sLNo = reinterpret_cast<float*>(smc + NOFF_LNO);
    float* sY   = reinterpret_cast<float*>(smc + NOFF_Y);

    if (tid < 128) sB1[tid] = node_b1[tid];
    if (tid < 64) { sB2[tid] = node_b2[tid]; sLNs[tid] = ln_scale[tid]; sLNo[tid] = ln_offset[tid]; }

    for (int i = tid; i < 128 * 128; i += 256) {
        const int n = i >> 7, k = i & 127;
        const float w = node_W1[k * 128 + n];
        const __nv_bfloat16 h = __float2bfloat16_rn(w);
        const __nv_bfloat16 l = __float2bfloat16_rn(w - __bfloat162float(h));
        *reinterpret_cast<__nv_bfloat16*>(smc + NOFF_W1H + (n * 136 + k) * 2) = h;
        *reinterpret_cast<__nv_bfloat16*>(smc + NOFF_W1L + (n * 136 + k) * 2) = l;
    }
    for (int i = tid; i < 64 * 128; i += 256) {
        const int n = i >> 7, k = i & 127;
        const float w = node_W2[k * 64 + n];
        const __nv_bfloat16 h = __float2bfloat16_rn(w);
        const __nv_bfloat16 l = __float2bfloat16_rn(w - __bfloat162float(h));
        *reinterpret_cast<__nv_bfloat16*>(smc + NOFF_W2H + (n * 136 + k) * 2) = h;
        *reinterpret_cast<__nv_bfloat16*>(smc + NOFF_W2L + (n * 136 + k) * 2) = l;
    }

    const int nbase = warp * 16;
    const int ncol0 = warp * 8;
    const int numTiles = (N_NODES + 127) / 128;  // 782

    for (int tile = blockIdx.x; tile < numTiles; tile += gridDim.x) {
        const int n0 = tile * 128;
        __syncthreads();

        {
            const int row  = tid >> 1;
            const int half = tid & 1;
            const int n    = n0 + row;
            const bool valid = n < N_NODES;
            const float* src = half ? &g_agg[(size_t)n * 64] : &nodes[(size_t)n * 64];
            const uint32_t base = (uint32_t)(row * 272 + half * 128);
            #pragma unroll
            for (int q = 0; q < 8; ++q) {
                float4 f0 = valid ? reinterpret_cast<const float4*>(src)[2 * q]
                                  : make_float4(0.f, 0.f, 0.f, 0.f);
                float4 f1 = valid ? reinterpret_cast<const float4*>(src)[2 * q + 1]
                                  : make_float4(0.f, 0.f, 0.f, 0.f);
                uint32_t hi[4], lo[4];
                bfsplit2(f0.x, f0.y, hi[0], lo[0]);
                bfsplit2(f0.z, f0.w, hi[1], lo[1]);
                bfsplit2(f1.x, f1.y, hi[2], lo[2]);
                bfsplit2(f1.z, f1.w, hi[3], lo[3]);
                *reinterpret_cast<uint4*>(smc + NOFF_XH + base + q * 16) =
                    make_uint4(hi[0], hi[1], hi[2], hi[3]);
                *reinterpret_cast<uint4*>(smc + NOFF_XL + base + q * 16) =
                    make_uint4(lo[0], lo[1], lo[2], lo[3]);
            }
        }
        __syncthreads();

        float acc[8][2][4];
        #pragma unroll
        for (int mt = 0; mt < 8; ++mt)
            #pragma unroll
            for (int nt = 0; nt < 2; ++nt) {
                const int n = nbase + nt * 8 + tg * 2;
                acc[mt][nt][0] = sB1[n];
                acc[mt][nt][1] = sB1[n + 1];
                acc[mt][nt][2] = sB1[n];
                acc[mt][nt][3] = sB1[n + 1];
            }
        #pragma unroll
        for (int kt = 0; kt < 8; ++kt) {
            const int k0 = kt * 16;
            uint32_t bh[2][2], bl[2][2];
            #pragma unroll
            for (int nt = 0; nt < 2; ++nt) {
                const uint32_t bo = (uint32_t)(((nbase + nt * 8 + g) * 136 + k0 + tg * 2) * 2);
                bh[nt][0] = *reinterpret_cast<const uint32_t*>(smc + NOFF_W1H + bo);
                bh[nt][1] = *reinterpret_cast<const uint32_t*>(smc + NOFF_W1H + bo + 16);
                bl[nt][0] = *reinterpret_cast<const uint32_t*>(smc + NOFF_W1L + bo);
                bl[nt][1] = *reinterpret_cast<const uint32_t*>(smc + NOFF_W1L + bo + 16);
            }
            #pragma unroll
            for (int mt = 0; mt < 8; ++mt) {
                const uint32_t ao = (uint32_t)(((mt * 16 + (qq & 1) * 8 + lr) * 136
                                                + k0 + (qq >> 1) * 8) * 2);
                uint32_t Ah[4], Al[4];
                ldmx4(Ah, sb + NOFF_XH + ao);
                ldmx4(Al, sb + NOFF_XL + ao);
                #pragma unroll
                for (int nt = 0; nt < 2; ++nt) {
                    mma16816(acc[mt][nt], Ah, bh[nt][0], bh[nt][1]);
                    mma16816(acc[mt][nt], Ah, bl[nt][0], bl[nt][1]);
                    mma16816(acc[mt][nt], Al, bh[nt][0], bh[nt][1]);
                }
            }
        }
        __syncthreads();

        #pragma unroll
        for (int mt = 0; mt < 8; ++mt) {
            const int er0 = mt * 16 + g, er1 = er0 + 8;
            #pragma unroll
            for (int nt = 0; nt < 2; ++nt) {
                const int n = nbase + nt * 8 + tg * 2;
                uint32_t hw, lw;
                bfsplit2(fmaxf(acc[mt][nt][0], 0.f), fmaxf(acc[mt][nt][1], 0.f), hw, lw);
                *reinterpret_cast<uint32_t*>(smc + NOFF_XH + er0 * 272 + n * 2) = hw;
                *reinterpret_cast<uint32_t*>(smc + NOFF_XL + er0 * 272 + n * 2) = lw;
                bfsplit2(fmaxf(acc[mt][nt][2], 0.f), fmaxf(acc[mt][nt][3], 0.f), hw, lw);
                *reinterpret_cast<uint32_t*>(smc + NOFF_XH + er1 * 272 + n * 2) = hw;
                *reinterpret_cast<uint32_t*>(smc + NOFF_XL + er1 * 272 + n * 2) = lw;
            }
        }
        __syncthreads();

        float acc2[8][4];
        {
            const int n = ncol0 + tg * 2;
            const float b0 = sB2[n], b1v = sB2[n + 1];
            #pragma unroll
            for (int mt = 0; mt < 8; ++mt) {
                acc2[mt][0] = b0; acc2[mt][1] = b1v;
                acc2[mt][2] = b0; acc2[mt][3] = b1v;
            }
        }
        #pragma unroll
        for (int kt = 0; kt < 8; ++kt) {
            const int k0 = kt * 16;
            const uint32_t bo = (uint32_t)(((ncol0 + g) * 136 + k0 + tg * 2) * 2);
            const uint32_t bh0 = *reinterpret_cast<const uint32_t*>(smc + NOFF_W2H + bo);
            const uint32_t bh1 = *reinterpret_cast<const uint32_t*>(smc + NOFF_W2H + bo + 16);
            const uint32_t bl0 = *reinterpret_cast<const uint32_t*>(smc + NOFF_W2L + bo);
            const uint32_t bl1 = *reinterpret_cast<const uint32_t*>(smc + NOFF_W2L + bo + 16);
            #pragma unroll
            for (int mt = 0; mt < 8; ++mt) {
                const uint32_t ao = (uint32_t)(((mt * 16 + (qq & 1) * 8 + lr) * 136
                                                + k0 + (qq >> 1) * 8) * 2);
                uint32_t Ah[4], Al[4];
                ldmx4(Ah, sb + NOFF_XH + ao);
                ldmx4(Al, sb + NOFF_XL + ao);
                mma16816(acc2[mt], Ah, bh0, bh1);
                mma16816(acc2[mt], Ah, bl0, bl1);
                mma16816(acc2[mt], Al, bh0, bh1);
            }
        }
        {
            const int n = ncol0 + tg * 2;
            #pragma unroll
            for (int mt = 0; mt < 8; ++mt) {
                const int er0 = mt * 16 + g, er1 = er0 + 8;
                sY[er0 * 68 + n]     = acc2[mt][0];
                sY[er0 * 68 + n + 1] = acc2[mt][1];
                sY[er1 * 68 + n]     = acc2[mt][2];
                sY[er1 * 68 + n + 1] = acc2[mt][3];
            }
        }
        __syncthreads();

        #pragma unroll
        for (int q = 0; q < 16; ++q) {
            const int i = warp * 16 + q;
            const int n = n0 + i;
            if (n >= N_NODES) break;
            const float v0 = sY[i * 68 + lane];
            const float v1 = sY[i * 68 + 32 + lane];
            float s  = v0 + v1;
            float sq = v0 * v0 + v1 * v1;
            #pragma unroll
            for (int off = 16; off; off >>= 1) {
                s  += __shfl_xor_sync(0xffffffffu, s,  off);
                sq += __shfl_xor_sync(0xffffffffu, sq, off);
            }
            const float mean = s * (1.f / 64.f);
            const float var  = sq * (1.f / 64.f) - mean * mean;
            const float rstd = rsqrtf(var + LN_EPS);
            out[(size_t)n * 64 + lane] =
                nodes[(size_t)n * 64 + lane] + (v0 - mean) * rstd * sLNs[lane] + sLNo[lane];
            out[(size_t)n * 64 + 32 + lane] =
                nodes[(size_t)n * 64 + 32 + lane] + (v1 - mean) * rstd * sLNs[32 + lane] + sLNo[32 + lane];
        }
    }
}

// =====================================================================
extern "C" void kernel_launch(void* const* d_in, const int* in_sizes, int n_in,
                              void* d_out, int out_size) {
    (void)in_sizes; (void)n_in; (void)out_size;
    const float* nodes     = (const float*)d_in[0];
    const float* edges     = (const float*)d_in[1];
    const int*   senders   = (const int*)d_in[2];
    const int*   receivers = (const int*)d_in[3];
    const float* msg_W1    = (const float*)d_in[4];
    const float* msg_b1    = (const float*)d_in[5];
    const float* msg_W2    = (const float*)d_in[6];
    const float* msg_b2    = (const float*)d_in[7];
    const float* node_W1   = (const float*)d_in[8];
    const float* node_b1   = (const float*)d_in[9];
    const float* node_W2   = (const float*)d_in[10];
    const float* node_b2   = (const float*)d_in[11];
    const float* ln_scale  = (const float*)d_in[12];
    const float* ln_offset = (const float*)d_in[13];
    float* out = (float*)d_out;

    cudaFuncSetAttribute(proj_kernel, cudaFuncAttributeMaxDynamicSharedMemorySize, (128 * 128 + 128) * 4);
    cudaFuncSetAttribute(edge_kernel, cudaFuncAttributeMaxDynamicSharedMemorySize, EDGE_SMEM_BYTES);
    cudaFuncSetAttribute(node_mma_kernel, cudaFuncAttributeMaxDynamicSharedMemorySize, NODE_SMEM_BYTES);

    zero_agg_kernel<<<256, 256>>>();
    proj_kernel<<<444, 256, (128 * 128 + 128) * 4>>>(nodes, msg_W1, msg_b1);
    edge_kernel<<<296, 256, EDGE_SMEM_BYTES>>>(edges, senders, receivers, msg_W1, msg_W2, msg_b2);
    node_mma_kernel<<<148, 256, NODE_SMEM_BYTES>>>(nodes, node_W1, node_b1, node_W2, node_b2,
                                                   ln_scale, ln_offset, out);
}

// round 17
// speedup vs baseline: 1.1103x; 1.1103x over previous
#include <cuda_runtime.h>
#include <cuda_bf16.h>
#include <cuda_fp16.h>
#include <cstdint>

// ---------------- fixed problem shapes ----------------
#define N_NODES 100000
#define D 64
#define E_EDGES 1600000
#define MSG_H 128
#define MSG_OUT 64
#define NODE_H 128
#define LN_EPS 1e-5f

// ---------------- device scratch ----------------
__device__ __align__(16) float g_Ps[(size_t)N_NODES * 128];  // nodes @ W1[0:64,:]
__device__ __align__(16) float g_Pr[(size_t)N_NODES * 128];  // nodes @ W1[64:128,:] + b1
__device__ __align__(16) float g_agg[(size_t)N_NODES * 64];  // segment-sum of messages

// =====================================================================
// helpers (sm_80/sm_90 baseline features -> compile for compute_103)
// =====================================================================
__device__ __forceinline__ uint32_t smem_u32(const void* p) {
    uint32_t a;
    asm("{ .reg .u64 t; cvta.to.shared.u64 t, %1; cvt.u32.u64 %0, t; }" : "=r"(a) : "l"(p));
    return a;
}

__device__ __forceinline__ void ldmx4(uint32_t* r, uint32_t addr) {
    asm volatile("ldmatrix.sync.aligned.m8n8.x4.shared.b16 {%0,%1,%2,%3}, [%4];"
                 : "=r"(r[0]), "=r"(r[1]), "=r"(r[2]), "=r"(r[3]) : "r"(addr));
}

// bf16 mma (node kernel)
__device__ __forceinline__ void mma16816(float* d, const uint32_t* a, uint32_t b0, uint32_t b1) {
    asm volatile(
        "mma.sync.aligned.m16n8k16.row.col.f32.bf16.bf16.f32 "
        "{%0,%1,%2,%3}, {%4,%5,%6,%7}, {%8,%9}, {%0,%1,%2,%3};"
        : "+f"(d[0]), "+f"(d[1]), "+f"(d[2]), "+f"(d[3])
        : "r"(a[0]), "r"(a[1]), "r"(a[2]), "r"(a[3]), "r"(b0), "r"(b1));
}

// fp16 mma (edge kernel)
__device__ __forceinline__ void mma16816h(float* d, const uint32_t* a, uint32_t b0, uint32_t b1) {
    asm volatile(
        "mma.sync.aligned.m16n8k16.row.col.f32.f16.f16.f32 "
        "{%0,%1,%2,%3}, {%4,%5,%6,%7}, {%8,%9}, {%0,%1,%2,%3};"
        : "+f"(d[0]), "+f"(d[1]), "+f"(d[2]), "+f"(d[3])
        : "r"(a[0]), "r"(a[1]), "r"(a[2]), "r"(a[3]), "r"(b0), "r"(b1));
}

__device__ __forceinline__ void bfsplit2(float x0, float x1, uint32_t& hi, uint32_t& lo) {
    __nv_bfloat162 h = __floats2bfloat162_rn(x0, x1);
    float r0 = x0 - __low2float(h);
    float r1 = x1 - __high2float(h);
    __nv_bfloat162 l = __floats2bfloat162_rn(r0, r1);
    hi = reinterpret_cast<uint32_t&>(h);
    lo = reinterpret_cast<uint32_t&>(l);
}

__device__ __forceinline__ void f16split2(float x0, float x1, uint32_t& hi, uint32_t& lo) {
    __half2 h = __floats2half2_rn(x0, x1);
    float r0 = x0 - __low2float(h);
    float r1 = x1 - __high2float(h);
    __half2 l = __floats2half2_rn(r0, r1);
    hi = reinterpret_cast<uint32_t&>(h);
    lo = reinterpret_cast<uint32_t&>(l);
}

__device__ __forceinline__ uint32_t f16pack2(float x0, float x1) {
    __half2 h = __floats2half2_rn(x0, x1);
    return reinterpret_cast<uint32_t&>(h);
}

__device__ __forceinline__ void red_add_v2(float* gptr, float a, float b) {
    asm volatile("red.global.add.v2.f32 [%0], {%1, %2};"
                 :: "l"(gptr), "f"(a), "f"(b) : "memory");
}

// =====================================================================
// Kernel 0: zero aggregation buffer
// =====================================================================
__global__ void zero_agg_kernel() {
    float4* p = reinterpret_cast<float4*>(g_agg);
    const int n4 = N_NODES * 64 / 4;
    for (int i = blockIdx.x * blockDim.x + threadIdx.x; i < n4; i += gridDim.x * blockDim.x)
        p[i] = make_float4(0.f, 0.f, 0.f, 0.f);
}

// =====================================================================
// Kernel 1: node projections (fp32 FFMA; 3.3 GFLOP total)
// =====================================================================
__global__ __launch_bounds__(256, 3)
void proj_kernel(const float* __restrict__ nodes,
                 const float* __restrict__ msg_W1,
                 const float* __restrict__ msg_b1)
{
    extern __shared__ float sm[];
    float* sW = sm;
    float* sN = sm + 128 * 128;

    const int tid = threadIdx.x;
    for (int i = tid; i < 128 * 128; i += 256) sW[i] = msg_W1[i];
    __syncthreads();

    const int sub = tid >> 7;
    const int c   = tid & 127;
    const float bias = msg_b1[c];

    const int numPairs = N_NODES / 2;
    for (int p = blockIdx.x; p < numPairs; p += gridDim.x) {
        const int n0 = p * 2;
        if (tid < 128) sN[tid] = nodes[(size_t)n0 * 64 + tid];
        __syncthreads();
        float as = 0.f, ar = 0.f;
        const float* nr = &sN[sub * 64];
        #pragma unroll 8
        for (int k = 0; k < 64; ++k) {
            const float a = nr[k];
            as = fmaf(a, sW[k * 128 + c], as);
            ar = fmaf(a, sW[(64 + k) * 128 + c], ar);
        }
        const int n = n0 + sub;
        g_Ps[(size_t)n * 128 + c] = as;
        g_Pr[(size_t)n * 128 + c] = ar + bias;
        __syncthreads();
    }
}

// =====================================================================
// Kernel 2: edge message MLP. R17 = R14 structure (128-edge tiles,
// 256 thr, M-split warps, gather hiding, v2 reg scatter) with fp16:
//   GEMM1 3-term (A hi/lo x W1 hi/lo), GEMM2 2-term (h single fp16).
//   -17% MMA, -50% GEMM2 ldmatrix, -50% h smem traffic vs R14.
// =====================================================================
#define OFF_B2   0
#define OFF_AH   256
#define OFF_AL   (OFF_AH  + 18432)
#define OFF_W1H  (OFF_AL  + 18432)
#define OFF_W1L  (OFF_W1H + 18432)
#define OFF_W2H  (OFF_W1L + 18432)
#define OFF_W2L  (OFF_W2H + 17408)
#define OFF_H    (OFF_W2L + 17408)
#define EDGE_SMEM_BYTES (OFF_H + 34816)   // 143616 bytes

__global__ __launch_bounds__(256, 1)
void edge_kernel(const float* __restrict__ edges,
                 const int* __restrict__ senders,
                 const int* __restrict__ receivers,
                 const float* __restrict__ msg_W1,
                 const float* __restrict__ msg_W2,
                 const float* __restrict__ msg_b2)
{
    extern __shared__ char smc[];
    const uint32_t sb = smem_u32(smc);
    const int tid  = threadIdx.x;
    const int warp = tid >> 5;        // 0..7 : 16-edge strip
    const int lane = tid & 31;
    const int g    = lane >> 2;       // groupID
    const int tg   = lane & 3;        // threadID-in-group
    const int qq   = lane >> 3;       // ldmatrix quadrant
    const int lr   = lane & 7;        // row within quadrant

    float* sB2 = reinterpret_cast<float*>(smc + OFF_B2);
    if (tid < 64) sB2[tid] = msg_b2[tid];

    // ---- stage W1e^T as [n=128][k=64] fp16 hi/lo, stride 72 ----
    for (int i = tid; i < 128 * 64; i += 256) {
        const int n = i >> 6, k = i & 63;
        const float w = msg_W1[(128 + k) * 128 + n];
        const __half h = __float2half_rn(w);
        const __half l = __float2half_rn(w - __half2float(h));
        *reinterpret_cast<__half*>(smc + OFF_W1H + (n * 72 + k) * 2) = h;
        *reinterpret_cast<__half*>(smc + OFF_W1L + (n * 72 + k) * 2) = l;
    }
    // ---- stage W2^T as [n=64][k=128] fp16 hi/lo, stride 136 ----
    for (int i = tid; i < 64 * 128; i += 256) {
        const int n = i >> 7, k = i & 127;
        const float w = msg_W2[k * 64 + n];
        const __half h = __float2half_rn(w);
        const __half l = __float2half_rn(w - __half2float(h));
        *reinterpret_cast<__half*>(smc + OFF_W2H + (n * 136 + k) * 2) = h;
        *reinterpret_cast<__half*>(smc + OFF_W2L + (n * 136 + k) * 2) = l;
    }

    const int er0 = warp * 16 + g;   // this lane's two edge rows
    const int er1 = er0 + 8;

    const int numTiles = E_EDGES / 128;  // 12500
    for (int tile = blockIdx.x; tile < numTiles; tile += gridDim.x) {
        const int e0 = tile * 128;

        // ---- ids via direct LDG (no smem roundtrip) ----
        const int s0 = __ldg(&senders[e0 + er0]);
        const int r0 = __ldg(&receivers[e0 + er0]);
        const int s1 = __ldg(&senders[e0 + er1]);
        const int r1 = __ldg(&receivers[e0 + er1]);

        // ---- issue Ps/Pr gathers NOW; they land during staging + GEMM1 ----
        float pg[16][4];
        {
            const float* ps0 = &g_Ps[(size_t)s0 * 128];
            const float* pr0 = &g_Pr[(size_t)r0 * 128];
            const float* ps1 = &g_Ps[(size_t)s1 * 128];
            const float* pr1 = &g_Pr[(size_t)r1 * 128];
            #pragma unroll
            for (int nf = 0; nf < 16; ++nf) {
                const int n = nf * 8 + tg * 2;
                const float2 a0 = *reinterpret_cast<const float2*>(ps0 + n);
                const float2 b0 = *reinterpret_cast<const float2*>(pr0 + n);
                const float2 a1 = *reinterpret_cast<const float2*>(ps1 + n);
                const float2 b1 = *reinterpret_cast<const float2*>(pr1 + n);
                pg[nf][0] = a0.x + b0.x;
                pg[nf][1] = a0.y + b0.y;
                pg[nf][2] = a1.x + b1.x;
                pg[nf][3] = a1.y + b1.y;
            }
        }

        __syncthreads();  // prior tile's smem reads complete

        // ---- stage edge tile [128][64] -> fp16 hi/lo (stride 72) ----
        #pragma unroll
        for (int cch = 0; cch < 2; ++cch) {
            const int c = tid + cch * 256;            // 0..511
            const int row = c >> 2, q = c & 3;        // q: 16-float chunk
            const float4* src = reinterpret_cast<const float4*>(
                &edges[(size_t)(e0 + row) * 64 + q * 16]);
            uint32_t hi[8], lo[8];
            #pragma unroll
            for (int j = 0; j < 4; ++j) {
                const float4 f = src[j];
                f16split2(f.x, f.y, hi[2 * j],     lo[2 * j]);
                f16split2(f.z, f.w, hi[2 * j + 1], lo[2 * j + 1]);
            }
            char* dh = smc + OFF_AH + row * 144 + q * 32;
            char* dl = smc + OFF_AL + row * 144 + q * 32;
            *reinterpret_cast<uint4*>(dh)      = make_uint4(hi[0], hi[1], hi[2], hi[3]);
            *reinterpret_cast<uint4*>(dh + 16) = make_uint4(hi[4], hi[5], hi[6], hi[7]);
            *reinterpret_cast<uint4*>(dl)      = make_uint4(lo[0], lo[1], lo[2], lo[3]);
            *reinterpret_cast<uint4*>(dl + 16) = make_uint4(lo[4], lo[5], lo[6], lo[7]);
        }
        __syncthreads();

        // ============ GEMM1 (3-term fp16): 16 edges x 128 cols ============
        float acc[16][4];
        #pragma unroll
        for (int nf = 0; nf < 16; ++nf)
            #pragma unroll
            for (int j = 0; j < 4; ++j) acc[nf][j] = 0.f;

        #pragma unroll
        for (int kt = 0; kt < 4; ++kt) {
            const int k0 = kt * 16;
            const uint32_t ao = (uint32_t)(((warp * 16 + (qq & 1) * 8 + lr) * 72
                                            + k0 + (qq >> 1) * 8) * 2);
            uint32_t Ah[4], Al[4];
            ldmx4(Ah, sb + OFF_AH + ao);
            ldmx4(Al, sb + OFF_AL + ao);
            #pragma unroll
            for (int nf = 0; nf < 16; ++nf) {
                const uint32_t bo = (uint32_t)(((nf * 8 + g) * 72 + k0 + tg * 2) * 2);
                const uint32_t bh0 = *reinterpret_cast<const uint32_t*>(smc + OFF_W1H + bo);
                const uint32_t bh1 = *reinterpret_cast<const uint32_t*>(smc + OFF_W1H + bo + 16);
                const uint32_t bl0 = *reinterpret_cast<const uint32_t*>(smc + OFF_W1L + bo);
                const uint32_t bl1 = *reinterpret_cast<const uint32_t*>(smc + OFF_W1L + bo + 16);
                mma16816h(acc[nf], Ah, bh0, bh1);
                mma16816h(acc[nf], Ah, bl0, bl1);
                mma16816h(acc[nf], Al, bh0, bh1);
            }
        }
        // epilogue1: += gathered Ps+Pr, relu -> SINGLE fp16 h (272 B rows)
        #pragma unroll
        for (int nf = 0; nf < 16; ++nf) {
            const int n = nf * 8 + tg * 2;
            *reinterpret_cast<uint32_t*>(smc + OFF_H + er0 * 272 + n * 2) =
                f16pack2(fmaxf(acc[nf][0] + pg[nf][0], 0.f),
                         fmaxf(acc[nf][1] + pg[nf][1], 0.f));
            *reinterpret_cast<uint32_t*>(smc + OFF_H + er1 * 272 + n * 2) =
                f16pack2(fmaxf(acc[nf][2] + pg[nf][2], 0.f),
                         fmaxf(acc[nf][3] + pg[nf][3], 0.f));
        }
        __syncthreads();

        // ============ GEMM2 (2-term fp16): 16 edges x 64 cols ============
        float acc2[8][4];
        #pragma unroll
        for (int nf = 0; nf < 8; ++nf) {
            const int n = nf * 8 + tg * 2;
            const float b0 = sB2[n], b1 = sB2[n + 1];
            acc2[nf][0] = b0; acc2[nf][1] = b1;
            acc2[nf][2] = b0; acc2[nf][3] = b1;
        }
        #pragma unroll
        for (int kt = 0; kt < 8; ++kt) {
            const int k0 = kt * 16;
            const uint32_t ao = (uint32_t)(((warp * 16 + (qq & 1) * 8 + lr) * 136
                                            + k0 + (qq >> 1) * 8) * 2);
            uint32_t Ah[4];
            ldmx4(Ah, sb + OFF_H + ao);
            #pragma unroll
            for (int nf = 0; nf < 8; ++nf) {
                const uint32_t bo = (uint32_t)(((nf * 8 + g) * 136 + k0 + tg * 2) * 2);
                const uint32_t bh0 = *reinterpret_cast<const uint32_t*>(smc + OFF_W2H + bo);
                const uint32_t bh1 = *reinterpret_cast<const uint32_t*>(smc + OFF_W2H + bo + 16);
                const uint32_t bl0 = *reinterpret_cast<const uint32_t*>(smc + OFF_W2L + bo);
                const uint32_t bl1 = *reinterpret_cast<const uint32_t*>(smc + OFF_W2L + bo + 16);
                mma16816h(acc2[nf], Ah, bh0, bh1);
                mma16816h(acc2[nf], Ah, bl0, bl1);
            }
        }
        // epilogue2: relu, vectorized scatter straight from registers
        #pragma unroll
        for (int nf = 0; nf < 8; ++nf) {
            const int n = nf * 8 + tg * 2;
            red_add_v2(&g_agg[(size_t)r0 * 64 + n],
                       fmaxf(acc2[nf][0], 0.f), fmaxf(acc2[nf][1], 0.f));
            red_add_v2(&g_agg[(size_t)r1 * 64 + n],
                       fmaxf(acc2[nf][2], 0.f), fmaxf(acc2[nf][3], 0.f));
        }
    }
}

// =====================================================================
// Kernel 3: node update MLP via warp-MMA (unchanged, ~94us)
// =====================================================================
#define NOFF_B1   0
#define NOFF_B2   512
#define NOFF_LNS  768
#define NOFF_LNO  1024
#define NOFF_W1H  1280
#define NOFF_W1L  (NOFF_W1H + 34816)
#define NOFF_W2H  (NOFF_W1L + 34816)
#define NOFF_W2L  (NOFF_W2H + 17408)
#define NOFF_XH   (NOFF_W2L + 17408)
#define NOFF_XL   (NOFF_XH  + 34816)
#define NOFF_Y    (NOFF_XL  + 34816)
#define NODE_SMEM_BYTES (NOFF_Y + 34816)   // 210176

__global__ __launch_bounds__(256, 1)
void node_mma_kernel(const float* __restrict__ nodes,
                     const float* __restrict__ node_W1,
                     const float* __restrict__ node_b1,
                     const float* __restrict__ node_W2,
                     const float* __restrict__ node_b2,
                     const float* __restrict__ ln_scale,
                     const float* __restrict__ ln_offset,
                     float* __restrict__ out)
{
    extern __shared__ char smc[];
    const uint32_t sb = smem_u32(smc);
    const int tid  = threadIdx.x;
    const int warp = tid >> 5;
    const int lane = tid & 31;
    const int g    = lane >> 2;
    const int tg   = lane & 3;
    const int qq   = lane >> 3;
    const int lr   = lane & 7;

    float* sB1  = reinterpret_cast<float*>(smc + NOFF_B1);
    float* sB2  = reinterpret_cast<float*>(smc + NOFF_B2);
    float* sLNs = reinterpret_cast<float*>(smc + NOFF_LNS);
    float* sLNo = reinterpret_cast<float*>(smc + NOFF_LNO);
    float* sY   = reinterpret_cast<float*>(smc + NOFF_Y);

    if (tid < 128) sB1[tid] = node_b1[tid];
    if (tid < 64) { sB2[tid] = node_b2[tid]; sLNs[tid] = ln_scale[tid]; sLNo[tid] = ln_offset[tid]; }

    for (int i = tid; i < 128 * 128; i += 256) {
        const int n = i >> 7, k = i & 127;
        const float w = node_W1[k * 128 + n];
        const __nv_bfloat16 h = __float2bfloat16_rn(w);
        const __nv_bfloat16 l = __float2bfloat16_rn(w - __bfloat162float(h));
        *reinterpret_cast<__nv_bfloat16*>(smc + NOFF_W1H + (n * 136 + k) * 2) = h;
        *reinterpret_cast<__nv_bfloat16*>(smc + NOFF_W1L + (n * 136 + k) * 2) = l;
    }
    for (int i = tid; i < 64 * 128; i += 256) {
        const int n = i >> 7, k = i & 127;
        const float w = node_W2[k * 64 + n];
        const __nv_bfloat16 h = __float2bfloat16_rn(w);
        const __nv_bfloat16 l = __float2bfloat16_rn(w - __bfloat162float(h));
        *reinterpret_cast<__nv_bfloat16*>(smc + NOFF_W2H + (n * 136 + k) * 2) = h;
        *reinterpret_cast<__nv_bfloat16*>(smc + NOFF_W2L + (n * 136 + k) * 2) = l;
    }

    const int nbase = warp * 16;
    const int ncol0 = warp * 8;
    const int numTiles = (N_NODES + 127) / 128;  // 782

    for (int tile = blockIdx.x; tile < numTiles; tile += gridDim.x) {
        const int n0 = tile * 128;
        __syncthreads();

        {
            const int row  = tid >> 1;
            const int half = tid & 1;
            const int n    = n0 + row;
            const bool valid = n < N_NODES;
            const float* src = half ? &g_agg[(size_t)n * 64] : &nodes[(size_t)n * 64];
            const uint32_t base = (uint32_t)(row * 272 + half * 128);
            #pragma unroll
            for (int q = 0; q < 8; ++q) {
                float4 f0 = valid ? reinterpret_cast<const float4*>(src)[2 * q]
                                  : make_float4(0.f, 0.f, 0.f, 0.f);
                float4 f1 = valid ? reinterpret_cast<const float4*>(src)[2 * q + 1]
                                  : make_float4(0.f, 0.f, 0.f, 0.f);
                uint32_t hi[4], lo[4];
                bfsplit2(f0.x, f0.y, hi[0], lo[0]);
                bfsplit2(f0.z, f0.w, hi[1], lo[1]);
                bfsplit2(f1.x, f1.y, hi[2], lo[2]);
                bfsplit2(f1.z, f1.w, hi[3], lo[3]);
                *reinterpret_cast<uint4*>(smc + NOFF_XH + base + q * 16) =
                    make_uint4(hi[0], hi[1], hi[2], hi[3]);
                *reinterpret_cast<uint4*>(smc + NOFF_XL + base + q * 16) =
                    make_uint4(lo[0], lo[1], lo[2], lo[3]);
            }
        }
        __syncthreads();

        float acc[8][2][4];
        #pragma unroll
        for (int mt = 0; mt < 8; ++mt)
            #pragma unroll
            for (int nt = 0; nt < 2; ++nt) {
                const int n = nbase + nt * 8 + tg * 2;
                acc[mt][nt][0] = sB1[n];
                acc[mt][nt][1] = sB1[n + 1];
                acc[mt][nt][2] = sB1[n];
                acc[mt][nt][3] = sB1[n + 1];
            }
        #pragma unroll
        for (int kt = 0; kt < 8; ++kt) {
            const int k0 = kt * 16;
            uint32_t bh[2][2], bl[2][2];
            #pragma unroll
            for (int nt = 0; nt < 2; ++nt) {
                const uint32_t bo = (uint32_t)(((nbase + nt * 8 + g) * 136 + k0 + tg * 2) * 2);
                bh[nt][0] = *reinterpret_cast<const uint32_t*>(smc + NOFF_W1H + bo);
                bh[nt][1] = *reinterpret_cast<const uint32_t*>(smc + NOFF_W1H + bo + 16);
                bl[nt][0] = *reinterpret_cast<const uint32_t*>(smc + NOFF_W1L + bo);
                bl[nt][1] = *reinterpret_cast<const uint32_t*>(smc + NOFF_W1L + bo + 16);
            }
            #pragma unroll
            for (int mt = 0; mt < 8; ++mt) {
                const uint32_t ao = (uint32_t)(((mt * 16 + (qq & 1) * 8 + lr) * 136
                                                + k0 + (qq >> 1) * 8) * 2);
                uint32_t Ah[4], Al[4];
                ldmx4(Ah, sb + NOFF_XH + ao);
                ldmx4(Al, sb + NOFF_XL + ao);
                #pragma unroll
                for (int nt = 0; nt < 2; ++nt) {
                    mma16816(acc[mt][nt], Ah, bh[nt][0], bh[nt][1]);
                    mma16816(acc[mt][nt], Ah, bl[nt][0], bl[nt][1]);
                    mma16816(acc[mt][nt], Al, bh[nt][0], bh[nt][1]);
                }
            }
        }
        __syncthreads();

        #pragma unroll
        for (int mt = 0; mt < 8; ++mt) {
            const int er0 = mt * 16 + g, er1 = er0 + 8;
            #pragma unroll
            for (int nt = 0; nt < 2; ++nt) {
                const int n = nbase + nt * 8 + tg * 2;
                uint32_t hw, lw;
                bfsplit2(fmaxf(acc[mt][nt][0], 0.f), fmaxf(acc[mt][nt][1], 0.f), hw, lw);
                *reinterpret_cast<uint32_t*>(smc + NOFF_XH + er0 * 272 + n * 2) = hw;
                *reinterpret_cast<uint32_t*>(smc + NOFF_XL + er0 * 272 + n * 2) = lw;
                bfsplit2(fmaxf(acc[mt][nt][2], 0.f), fmaxf(acc[mt][nt][3], 0.f), hw, lw);
                *reinterpret_cast<uint32_t*>(smc + NOFF_XH + er1 * 272 + n * 2) = hw;
                *reinterpret_cast<uint32_t*>(smc + NOFF_XL + er1 * 272 + n * 2) = lw;
            }
        }
        __syncthreads();

        float acc2[8][4];
        {
            const int n = ncol0 + tg * 2;
            const float b0 = sB2[n], b1v = sB2[n + 1];
            #pragma unroll
            for (int mt = 0; mt < 8; ++mt) {
                acc2[mt][0] = b0; acc2[mt][1] = b1v;
                acc2[mt][2] = b0; acc2[mt][3] = b1v;
            }
        }
        #pragma unroll
        for (int kt = 0; kt < 8; ++kt) {
            const int k0 = kt * 16;
            const uint32_t bo = (uint32_t)(((ncol0 + g) * 136 + k0 + tg * 2) * 2);
            const uint32_t bh0 = *reinterpret_cast<const uint32_t*>(smc + NOFF_W2H + bo);
            const uint32_t bh1 = *reinterpret_cast<const uint32_t*>(smc + NOFF_W2H + bo + 16);
            const uint32_t bl0 = *reinterpret_cast<const uint32_t*>(smc + NOFF_W2L + bo);
            const uint32_t bl1 = *reinterpret_cast<const uint32_t*>(smc + NOFF_W2L + bo + 16);
            #pragma unroll
            for (int mt = 0; mt < 8; ++mt) {
                const uint32_t ao = (uint32_t)(((mt * 16 + (qq & 1) * 8 + lr) * 136
                                                + k0 + (qq >> 1) * 8) * 2);
                uint32_t Ah[4], Al[4];
                ldmx4(Ah, sb + NOFF_XH + ao);
                ldmx4(Al, sb + NOFF_XL + ao);
                mma16816(acc2[mt], Ah, bh0, bh1);
                mma16816(acc2[mt], Ah, bl0, bl1);
                mma16816(acc2[mt], Al, bh0, bh1);
            }
        }
        {
            const int n = ncol0 + tg * 2;
            #pragma unroll
            for (int mt = 0; mt < 8; ++mt) {
                const int er0 = mt * 16 + g, er1 = er0 + 8;
                sY[er0 * 68 + n]     = acc2[mt][0];
                sY[er0 * 68 + n + 1] = acc2[mt][1];
                sY[er1 * 68 + n]     = acc2[mt][2];
                sY[er1 * 68 + n + 1] = acc2[mt][3];
            }
        }
        __syncthreads();

        #pragma unroll
        for (int q = 0; q < 16; ++q) {
            const int i = warp * 16 + q;
            const int n = n0 + i;
            if (n >= N_NODES) break;
            const float v0 = sY[i * 68 + lane];
            const float v1 = sY[i * 68 + 32 + lane];
            float s  = v0 + v1;
            float sq = v0 * v0 + v1 * v1;
            #pragma unroll
            for (int off = 16; off; off >>= 1) {
                s  += __shfl_xor_sync(0xffffffffu, s,  off);
                sq += __shfl_xor_sync(0xffffffffu, sq, off);
            }
            const float mean = s * (1.f / 64.f);
            const float var  = sq * (1.f / 64.f) - mean * mean;
            const float rstd = rsqrtf(var + LN_EPS);
            out[(size_t)n * 64 + lane] =
                nodes[(size_t)n * 64 + lane] + (v0 - mean) * rstd * sLNs[lane] + sLNo[lane];
            out[(size_t)n * 64 + 32 + lane] =
                nodes[(size_t)n * 64 + 32 + lane] + (v1 - mean) * rstd * sLNs[32 + lane] + sLNo[32 + lane];
        }
    }
}

// =====================================================================
extern "C" void kernel_launch(void* const* d_in, const int* in_sizes, int n_in,
                              void* d_out, int out_size) {
    (void)in_sizes; (void)n_in; (void)out_size;
    const float* nodes     = (const float*)d_in[0];
    const float* edges     = (const float*)d_in[1];
    const int*   senders   = (const int*)d_in[2];
    const int*   receivers = (const int*)d_in[3];
    const float* msg_W1    = (const float*)d_in[4];
    const float* msg_b1    = (const float*)d_in[5];
    const float* msg_W2    = (const float*)d_in[6];
    const float* msg_b2    = (const float*)d_in[7];
    const float* node_W1   = (const float*)d_in[8];
    const float* node_b1   = (const float*)d_in[9];
    const float* node_W2   = (const float*)d_in[10];
    const float* node_b2   = (const float*)d_in[11];
    const float* ln_scale  = (const float*)d_in[12];
    const float* ln_offset = (const float*)d_in[13];
    float* out = (float*)d_out;

    cudaFuncSetAttribute(proj_kernel, cudaFuncAttributeMaxDynamicSharedMemorySize, (128 * 128 + 128) * 4);
    cudaFuncSetAttribute(edge_kernel, cudaFuncAttributeMaxDynamicSharedMemorySize, EDGE_SMEM_BYTES);
    cudaFuncSetAttribute(node_mma_kernel, cudaFuncAttributeMaxDynamicSharedMemorySize, NODE_SMEM_BYTES);

    zero_agg_kernel<<<256, 256>>>();
    proj_kernel<<<444, 256, (128 * 128 + 128) * 4>>>(nodes, msg_W1, msg_b1);
    edge_kernel<<<148, 256, EDGE_SMEM_BYTES>>>(edges, senders, receivers, msg_W1, msg_W2, msg_b2);
    node_mma_kernel<<<148, 256, NODE_SMEM_BYTES>>>(nodes, node_W1, node_b1, node_W2, node_b2,
                                                   ln_scale, ln_offset, out);
}